// round 5
// baseline (speedup 1.0000x reference)
#include <cuda_runtime.h>
#include <math.h>

#define BB 2
#define NN 4096
#define KK 30

#define SZ_POS (BB*NN*KK*16)
#define SZ_AD  (BB*NN*3)
#define SZ_OF  (BB*NN*KK*3)
#define SZ_GS  (BB*NN*KK*15)
#define SZ_DN  (BB*NN*KK)

#define OFF_POS 0
#define OFF_AD  (OFF_POS + SZ_POS)
#define OFF_OF  (OFF_AD  + SZ_AD)
#define OFF_GS  (OFF_OF  + SZ_OF)
#define OFF_DN  (OFF_GS  + SZ_GS)
#define OFF_EI  (OFF_DN  + SZ_DN)

// ---- scratch (no allocations allowed) ----
static __device__ int   g_eidx[BB*NN*KK];
static __device__ float g_Omat[BB*NN*9];
static __device__ float g_freq[8];
static __device__ float g_mu[15];

// ---- exact-rounding helpers (block FMA contraction / fast-math) ----
__device__ __forceinline__ float fadd_(float a, float b){ return __fadd_rn(a,b); }
__device__ __forceinline__ float fsub_(float a, float b){ return __fsub_rn(a,b); }
__device__ __forceinline__ float fmul_(float a, float b){ return __fmul_rn(a,b); }
__device__ __forceinline__ float dot3_(float ax,float ay,float az,
                                       float bx,float by,float bz){
    return fadd_(fadd_(fmul_(ax,bx), fmul_(ay,by)), fmul_(az,bz));
}
__device__ __forceinline__ void norm3_(float &x, float &y, float &z){
    float n = __fsqrt_rn(dot3_(x,y,z,x,y,z));
    n = fmaxf(n, 1e-12f);
    x = __fdiv_rn(x,n); y = __fdiv_rn(y,n); z = __fdiv_rn(z,n);
}
__device__ __forceinline__ void cross3_(float ax,float ay,float az,
                                        float bx,float by,float bz,
                                        float &cx,float &cy,float &cz){
    cx = fsub_(fmul_(ay,bz), fmul_(az,by));
    cy = fsub_(fmul_(az,bx), fmul_(ax,bz));
    cz = fsub_(fmul_(ax,by), fmul_(ay,bx));
}
__device__ __forceinline__ float d2_exact(float xi,float yi,float zi,
                                          float xj,float yj,float zj){
    float dx = fsub_(xj,xi), dy = fsub_(yj,yi), dz = fsub_(zj,zi);
    return fadd_(fadd_(fmul_(dx,dx), fmul_(dy,dy)), fmul_(dz,dz));
}

// ---- FP32 Cody-Waite 2pi reduction + MUFU sin/cos ----
#define INV_2PI  0.15915494309189535f
#define PI2_C1   6.2831855f
#define PI2_C2  -1.7484555e-07f
#define PI2_C3  -5.4469782e-15f
__device__ __forceinline__ void sincos_red_(float ang, float &s, float &c){
    float k = rintf(ang * INV_2PI);
    float r = fmaf(-k, PI2_C1, ang);
    r = fmaf(-k, PI2_C2, r);
    r = fmaf(-k, PI2_C3, r);
    s = __sinf(r);
    c = __cosf(r);
}

// ============================================================================
// Kernel A v3: exact top-30 kNN.
// 4 warps/block, 4 rows/warp (register-resident), register histograms
// (16 octave bins x 8-bit fields in 2 x u64 per row), direct LDG coords
// (L1-resident), ballot compaction of (d2,j), exact (D,j)-keyed extraction.
// ============================================================================
#define TPB3  128
#define RWARP 4
#define RBLK  16          // rows per block
#define CAP3  192
#define QMAX3 6

__global__ __launch_bounds__(TPB3, 4) void knn_kernel(
    const float* __restrict__ X, float* __restrict__ outD, float* __restrict__ outE)
{
    __shared__ unsigned long long cand[RBLK][CAP3];

    const int t = threadIdx.x, w = t >> 5, lane = t & 31;
    const int blk = blockIdx.x;
    const int b   = blk / (NN/RBLK);
    const int r0  = (blk % (NN/RBLK))*RBLK + w*RWARP;
    const float* Xb = X + b*NN*3;

    float xi[RWARP], yi[RWARP], zi[RWARP];
    #pragma unroll
    for (int r = 0; r < RWARP; r++){
        xi[r] = Xb[(r0+r)*3+0];
        yi[r] = Xb[(r0+r)*3+1];
        zi[r] = Xb[(r0+r)*3+2];
    }

    unsigned long long h0[RWARP], h1[RWARP];
    #pragma unroll
    for (int r = 0; r < RWARP; r++){ h0[r]=0ull; h1[r]=0ull; }

    // ---- pass 1: register histogram of d^2 octave bins ----
    #pragma unroll 2
    for (int m = 0; m < NN/32; m++){
        int j = m*32 + lane;
        float xj = __ldg(&Xb[j*3+0]);
        float yj = __ldg(&Xb[j*3+1]);
        float zj = __ldg(&Xb[j*3+2]);
        #pragma unroll
        for (int r = 0; r < RWARP; r++){
            float d2 = d2_exact(xi[r],yi[r],zi[r],xj,yj,zj);
            int bin = (int)(__float_as_uint(d2) >> 23) - 126;
            bin = max(0, min(15, bin));
            unsigned long long one = 1ull << ((bin & 7) << 3);
            if (bin < 8) h0[r] += one; else h1[r] += one;
        }
    }

    // ---- per-row threshold bin via warp tree over packed counters ----
    int Tb[RWARP];
    const unsigned long long M8 = 0x00FF00FF00FF00FFull;
    #pragma unroll
    for (int r = 0; r < RWARP; r++){
        unsigned long long a0 =  h0[r]       & M8;   // bins 0,2,4,6
        unsigned long long a1 = (h0[r] >> 8) & M8;   // bins 1,3,5,7
        unsigned long long a2 =  h1[r]       & M8;   // bins 8,10,12,14
        unsigned long long a3 = (h1[r] >> 8) & M8;   // bins 9,11,13,15
        #pragma unroll
        for (int off = 16; off; off >>= 1){
            a0 += __shfl_xor_sync(0xffffffffu, a0, off);
            a1 += __shfl_xor_sync(0xffffffffu, a1, off);
            a2 += __shfl_xor_sync(0xffffffffu, a2, off);
            a3 += __shfl_xor_sync(0xffffffffu, a3, off);
        }
        int cum = 0, T = 15;
        #pragma unroll
        for (int bb = 0; bb < 16; bb++){
            unsigned long long src = (bb < 8) ? ((bb & 1) ? a1 : a0)
                                              : ((bb & 1) ? a3 : a2);
            cum += (int)((src >> (((bb >> 1) & 3) << 4)) & 0xFFFFull);
            if (cum >= KK){ T = bb; break; }
        }
        Tb[r] = T;
    }

    // ---- pass 2: compact survivors (d2bits<<32 | j) via ballot prefix ----
    int cnt[RWARP];
    #pragma unroll
    for (int r = 0; r < RWARP; r++) cnt[r] = 0;

    #pragma unroll 2
    for (int m = 0; m < NN/32; m++){
        int j = m*32 + lane;
        float xj = __ldg(&Xb[j*3+0]);
        float yj = __ldg(&Xb[j*3+1]);
        float zj = __ldg(&Xb[j*3+2]);
        #pragma unroll
        for (int r = 0; r < RWARP; r++){
            float d2 = d2_exact(xi[r],yi[r],zi[r],xj,yj,zj);
            int bin = (int)(__float_as_uint(d2) >> 23) - 126;
            bin = max(0, min(15, bin));
            bool keep = (bin <= Tb[r]);
            unsigned int mask = __ballot_sync(0xffffffffu, keep);
            if (keep){
                int pos = cnt[r] + __popc(mask & ((1u << lane) - 1u));
                if (pos < CAP3)
                    cand[w*RWARP + r][pos] =
                        ((unsigned long long)__float_as_uint(d2) << 32) | (unsigned int)j;
            }
            cnt[r] += __popc(mask);
        }
    }
    __syncwarp();

    // ---- extraction: 30 ordered mins under exact (D, j) key ----
    const unsigned long long UMAX = 0xFFFFFFFFFFFFFFFFull;
    #pragma unroll
    for (int r = 0; r < RWARP; r++){
        int c = min(cnt[r], CAP3);
        unsigned long long kq[QMAX3];
        #pragma unroll
        for (int q = 0; q < QMAX3; q++){
            int idx = q*32 + lane;
            if (idx < c){
                unsigned long long raw = cand[w*RWARP + r][idx];
                float d2 = __uint_as_float((unsigned int)(raw >> 32));
                float D  = __fsqrt_rn(fadd_(d2, 1e-6f));
                kq[q] = ((unsigned long long)__float_as_uint(D) << 32)
                      | (raw & 0xFFFFFFFFull);
            } else kq[q] = UMAX;
        }
        unsigned long long lm = kq[0]; int ls = 0;
        #pragma unroll
        for (int q = 1; q < QMAX3; q++) if (kq[q] < lm){ lm = kq[q]; ls = q; }

        const int base = (b*NN + r0 + r)*KK;
        for (int k = 0; k < KK; k++){
            unsigned long long v = lm;
            #pragma unroll
            for (int off = 16; off; off >>= 1){
                unsigned long long o = __shfl_xor_sync(0xffffffffu, v, off);
                if (o < v) v = o;
            }
            if (lane == 0){
                unsigned int jj = (unsigned int)(v & 0xFFFFFFFFull);
                outD[base + k]   = __uint_as_float((unsigned int)(v >> 32));
                outE[base + k]   = (float)jj;
                g_eidx[base + k] = (int)jj;
            }
            if (lm == v){
                #pragma unroll
                for (int q = 0; q < QMAX3; q++) if (q == ls) kq[q] = UMAX;
                lm = kq[0]; ls = 0;
                #pragma unroll
                for (int q = 1; q < QMAX3; q++) if (kq[q] < lm){ lm = kq[q]; ls = q; }
            }
        }
    }
}

// ============================================================================
// Kernel B: per-node orientation matrix O + AD features (+ const init)
// ============================================================================
__global__ void node_kernel(const float* __restrict__ X, float* __restrict__ outAD){
    int id = blockIdx.x*blockDim.x + threadIdx.x;
    if (blockIdx.x == 0){
        int tt2 = threadIdx.x;
        if (tt2 < 8){
            float argf = __fmul_rn((float)(2*tt2), -0.5756462732485115f);
            g_freq[tt2] = (float)exp((double)argf);
        }
        if (tt2 < 15) g_mu[tt2] = (float)((double)tt2 * (20.0/14.0));
    }
    if (id >= BB*NN) return;
    int b = id / NN, n = id % NN;

    float O0=0,O1=0,O2=0,O3v=0,O4=0,O5=0,O6=0,O7=0,O8=0;
    float a0=0,a1=0,a2=0;

    if (n >= 1 && n <= NN-3){
        const float* Xb = X + b*NN*3;
        float p0x=Xb[(n-1)*3+0], p0y=Xb[(n-1)*3+1], p0z=Xb[(n-1)*3+2];
        float p1x=Xb[(n  )*3+0], p1y=Xb[(n  )*3+1], p1z=Xb[(n  )*3+2];
        float p2x=Xb[(n+1)*3+0], p2y=Xb[(n+1)*3+1], p2z=Xb[(n+1)*3+2];
        float p3x=Xb[(n+2)*3+0], p3y=Xb[(n+2)*3+1], p3z=Xb[(n+2)*3+2];

        float u2x=fsub_(p1x,p0x), u2y=fsub_(p1y,p0y), u2z=fsub_(p1z,p0z); norm3_(u2x,u2y,u2z);
        float u1x=fsub_(p2x,p1x), u1y=fsub_(p2y,p1y), u1z=fsub_(p2z,p1z); norm3_(u1x,u1y,u1z);
        float u0x=fsub_(p3x,p2x), u0y=fsub_(p3y,p2y), u0z=fsub_(p3z,p2z); norm3_(u0x,u0y,u0z);

        float n2x,n2y,n2z; cross3_(u2x,u2y,u2z,u1x,u1y,u1z,n2x,n2y,n2z); norm3_(n2x,n2y,n2z);
        float n1x,n1y,n1z; cross3_(u1x,u1y,u1z,u0x,u0y,u0z,n1x,n1y,n1z); norm3_(n1x,n1y,n1z);

        const float lo = (float)(-1.0 + 1e-6);
        const float hi = (float)( 1.0 - 1e-6);
        float cosA = fminf(fmaxf(-dot3_(u1x,u1y,u1z,u0x,u0y,u0z), lo), hi);
        float A = acosf(cosA);
        float cosD = fminf(fmaxf(dot3_(n2x,n2y,n2z,n1x,n1y,n1z), lo), hi);
        float s = dot3_(u2x,u2y,u2z,n1x,n1y,n1z);
        float sg = (s > 0.0f) ? 1.0f : ((s < 0.0f) ? -1.0f : 0.0f);
        float Dang = fmul_(sg, acosf(cosD));

        float sA = sinf(A);
        a0 = cosf(A);
        a1 = fmul_(sA, cosf(Dang));
        a2 = fmul_(sA, sinf(Dang));

        float o1x=fsub_(u2x,u1x), o1y=fsub_(u2y,u1y), o1z=fsub_(u2z,u1z); norm3_(o1x,o1y,o1z);
        float cx,cy,cz; cross3_(o1x,o1y,o1z,n2x,n2y,n2z,cx,cy,cz);
        O0=o1x; O1=o1y; O2=o1z; O3v=n2x; O4=n2y; O5=n2z; O6=cx; O7=cy; O8=cz;
    }
    float* Om = g_Omat + id*9;
    Om[0]=O0; Om[1]=O1; Om[2]=O2; Om[3]=O3v; Om[4]=O4; Om[5]=O5; Om[6]=O6; Om[7]=O7; Om[8]=O8;
    outAD[id*3+0]=a0; outAD[id*3+1]=a1; outAD[id*3+2]=a2;
}

// ============================================================================
// Kernel C (merged): per-edge pos_emb (16) + gaussian smear (15) + dU (3)
// ============================================================================
#define LOG2E 1.4426950408889634f
__global__ __launch_bounds__(256) void edge_kernel(
    const float* __restrict__ X, const float* __restrict__ Dn,
    float* __restrict__ outP, float* __restrict__ outG, float* __restrict__ outO)
{
    int e = blockIdx.x*blockDim.x + threadIdx.x;
    if (e >= BB*NN*KK) return;
    int ni = e / KK;
    int i  = ni % NN;
    int b  = ni / NN;
    int j  = g_eidx[e];

    // ---- positional encodings ----
    float d = fsub_((float)j, (float)i);
    float co[8], si[8];
    #pragma unroll
    for (int m = 0; m < 8; m++){
        float ang = fmul_(d, g_freq[m]);
        sincos_red_(ang, si[m], co[m]);
    }
    float4* op = (float4*)(outP + (size_t)e*16);
    op[0] = make_float4(co[0],co[1],co[2],co[3]);
    op[1] = make_float4(co[4],co[5],co[6],co[7]);
    op[2] = make_float4(si[0],si[1],si[2],si[3]);
    op[3] = make_float4(si[4],si[5],si[6],si[7]);

    // ---- gaussian smearing ----
    float D = __ldg(&Dn[e]);
    float* og = outG + (size_t)e*15;
    #pragma unroll
    for (int m = 0; m < 15; m++){
        float tt = __fdiv_rn(fsub_(D, g_mu[m]), 1.3333333333333333f);
        og[m] = exp2f(-fmul_(tt,tt) * LOG2E);
    }

    // ---- dU ----
    const float* Xb = X + b*NN*3;
    float dx = fsub_(Xb[j*3+0], Xb[i*3+0]);
    float dy = fsub_(Xb[j*3+1], Xb[i*3+1]);
    float dz = fsub_(Xb[j*3+2], Xb[i*3+2]);
    const float* Om = g_Omat + (size_t)ni*9;
    float v0 = dot3_(Om[0],Om[1],Om[2], dx,dy,dz);
    float v1 = dot3_(Om[3],Om[4],Om[5], dx,dy,dz);
    float v2 = dot3_(Om[6],Om[7],Om[8], dx,dy,dz);
    float n = __fsqrt_rn(dot3_(v0,v1,v2,v0,v1,v2));
    n = fmaxf(n, 1e-12f);
    outO[(size_t)e*3+0] = __fdiv_rn(v0,n);
    outO[(size_t)e*3+1] = __fdiv_rn(v1,n);
    outO[(size_t)e*3+2] = __fdiv_rn(v2,n);
}

// ============================================================================
extern "C" void kernel_launch(void* const* d_in, const int* in_sizes, int n_in,
                              void* d_out, int out_size)
{
    const float* X = (const float*)d_in[0];
    float* out = (float*)d_out;

    node_kernel<<<(BB*NN + 255)/256, 256>>>(X, out + OFF_AD);
    knn_kernel<<<BB*NN/RBLK, TPB3>>>(X, out + OFF_DN, out + OFF_EI);
    edge_kernel<<<(BB*NN*KK + 255)/256, 256>>>(X, out + OFF_DN,
                                               out + OFF_POS, out + OFF_GS, out + OFF_OF);
}

// round 6
// speedup vs baseline: 1.2371x; 1.2371x over previous
#include <cuda_runtime.h>
#include <math.h>

#define BB 2
#define NN 4096
#define KK 30

#define SZ_POS (BB*NN*KK*16)
#define SZ_AD  (BB*NN*3)
#define SZ_OF  (BB*NN*KK*3)
#define SZ_GS  (BB*NN*KK*15)
#define SZ_DN  (BB*NN*KK)

#define OFF_POS 0
#define OFF_AD  (OFF_POS + SZ_POS)
#define OFF_OF  (OFF_AD  + SZ_AD)
#define OFF_GS  (OFF_OF  + SZ_OF)
#define OFF_DN  (OFF_GS  + SZ_GS)
#define OFF_EI  (OFF_DN  + SZ_DN)

// ---- scratch (no allocations allowed) ----
static __device__ int   g_eidx[BB*NN*KK];
static __device__ float g_Omat[BB*NN*9];
static __device__ float g_freq[8];
static __device__ float g_mu[15];

// ---- exact-rounding helpers (block FMA contraction / fast-math) ----
__device__ __forceinline__ float fadd_(float a, float b){ return __fadd_rn(a,b); }
__device__ __forceinline__ float fsub_(float a, float b){ return __fsub_rn(a,b); }
__device__ __forceinline__ float fmul_(float a, float b){ return __fmul_rn(a,b); }
__device__ __forceinline__ float dot3_(float ax,float ay,float az,
                                       float bx,float by,float bz){
    return fadd_(fadd_(fmul_(ax,bx), fmul_(ay,by)), fmul_(az,bz));
}
__device__ __forceinline__ void norm3_(float &x, float &y, float &z){
    float n = __fsqrt_rn(dot3_(x,y,z,x,y,z));
    n = fmaxf(n, 1e-12f);
    x = __fdiv_rn(x,n); y = __fdiv_rn(y,n); z = __fdiv_rn(z,n);
}
__device__ __forceinline__ void cross3_(float ax,float ay,float az,
                                        float bx,float by,float bz,
                                        float &cx,float &cy,float &cz){
    cx = fsub_(fmul_(ay,bz), fmul_(az,by));
    cy = fsub_(fmul_(az,bx), fmul_(ax,bz));
    cz = fsub_(fmul_(ax,by), fmul_(ay,bx));
}
__device__ __forceinline__ float d2_exact(float xi,float yi,float zi,
                                          float xj,float yj,float zj){
    float dx = fsub_(xj,xi), dy = fsub_(yj,yi), dz = fsub_(zj,zi);
    return fadd_(fadd_(fmul_(dx,dx), fmul_(dy,dy)), fmul_(dz,dz));
}

// ---- FP32 Cody-Waite 2pi reduction + MUFU sin/cos ----
#define INV_2PI  0.15915494309189535f
#define PI2_C1   6.2831855f
#define PI2_C2  -1.7484555e-07f
#define PI2_C3  -5.4469782e-15f
__device__ __forceinline__ void sincos_red_(float ang, float &s, float &c){
    float k = rintf(ang * INV_2PI);
    float r = fmaf(-k, PI2_C1, ang);
    r = fmaf(-k, PI2_C2, r);
    r = fmaf(-k, PI2_C3, r);
    s = __sinf(r);
    c = __cosf(r);
}

// ---- per-node orientation matrix + AD (device function, fused into knn) ----
__device__ void node_work(const float* __restrict__ X, float* __restrict__ outAD, int id){
    int b = id / NN, n = id % NN;

    float O0=0,O1=0,O2=0,O3v=0,O4=0,O5=0,O6=0,O7=0,O8=0;
    float a0=0,a1=0,a2=0;

    if (n >= 1 && n <= NN-3){
        const float* Xb = X + b*NN*3;
        float p0x=Xb[(n-1)*3+0], p0y=Xb[(n-1)*3+1], p0z=Xb[(n-1)*3+2];
        float p1x=Xb[(n  )*3+0], p1y=Xb[(n  )*3+1], p1z=Xb[(n  )*3+2];
        float p2x=Xb[(n+1)*3+0], p2y=Xb[(n+1)*3+1], p2z=Xb[(n+1)*3+2];
        float p3x=Xb[(n+2)*3+0], p3y=Xb[(n+2)*3+1], p3z=Xb[(n+2)*3+2];

        float u2x=fsub_(p1x,p0x), u2y=fsub_(p1y,p0y), u2z=fsub_(p1z,p0z); norm3_(u2x,u2y,u2z);
        float u1x=fsub_(p2x,p1x), u1y=fsub_(p2y,p1y), u1z=fsub_(p2z,p1z); norm3_(u1x,u1y,u1z);
        float u0x=fsub_(p3x,p2x), u0y=fsub_(p3y,p2y), u0z=fsub_(p3z,p2z); norm3_(u0x,u0y,u0z);

        float n2x,n2y,n2z; cross3_(u2x,u2y,u2z,u1x,u1y,u1z,n2x,n2y,n2z); norm3_(n2x,n2y,n2z);
        float n1x,n1y,n1z; cross3_(u1x,u1y,u1z,u0x,u0y,u0z,n1x,n1y,n1z); norm3_(n1x,n1y,n1z);

        const float lo = (float)(-1.0 + 1e-6);
        const float hi = (float)( 1.0 - 1e-6);
        float cosA = fminf(fmaxf(-dot3_(u1x,u1y,u1z,u0x,u0y,u0z), lo), hi);
        float A = acosf(cosA);
        float cosD = fminf(fmaxf(dot3_(n2x,n2y,n2z,n1x,n1y,n1z), lo), hi);
        float s = dot3_(u2x,u2y,u2z,n1x,n1y,n1z);
        float sg = (s > 0.0f) ? 1.0f : ((s < 0.0f) ? -1.0f : 0.0f);
        float Dang = fmul_(sg, acosf(cosD));

        float sA = sinf(A);
        a0 = cosf(A);
        a1 = fmul_(sA, cosf(Dang));
        a2 = fmul_(sA, sinf(Dang));

        float o1x=fsub_(u2x,u1x), o1y=fsub_(u2y,u1y), o1z=fsub_(u2z,u1z); norm3_(o1x,o1y,o1z);
        float cx,cy,cz; cross3_(o1x,o1y,o1z,n2x,n2y,n2z,cx,cy,cz);
        O0=o1x; O1=o1y; O2=o1z; O3v=n2x; O4=n2y; O5=n2z; O6=cx; O7=cy; O8=cz;
    }
    float* Om = g_Omat + id*9;
    Om[0]=O0; Om[1]=O1; Om[2]=O2; Om[3]=O3v; Om[4]=O4; Om[5]=O5; Om[6]=O6; Om[7]=O7; Om[8]=O8;
    outAD[id*3+0]=a0; outAD[id*3+1]=a1; outAD[id*3+2]=a2;
}

// ============================================================================
// Kernel A v4: exact top-30 kNN + fused node work.
// 4 warps/block, 4 rows/warp register-resident, register octave histograms,
// ballot compaction of (d2,j), RANK-BASED extraction (no shuffle chains).
// ============================================================================
#define TPB3  128
#define RWARP 4
#define RBLK  16
#define CAP3  192

__global__ __launch_bounds__(TPB3, 4) void knn_kernel(
    const float* __restrict__ X, float* __restrict__ outD, float* __restrict__ outE,
    float* __restrict__ outAD)
{
    __shared__ unsigned long long cand[RBLK][CAP3];   // 24KB

    const int t = threadIdx.x, w = t >> 5, lane = t & 31;
    const int blk = blockIdx.x;
    const int b   = blk / (NN/RBLK);
    const int r0  = (blk % (NN/RBLK))*RBLK + w*RWARP;
    const float* Xb = X + b*NN*3;

    // ---- fused node work: 16 node ids per block, threads 0..15 ----
    if (t < 16){
        node_work(X, outAD, blk*16 + t);
        if (blk == 0){
            if (t < 8){
                float argf = __fmul_rn((float)(2*t), -0.5756462732485115f);
                g_freq[t] = (float)exp((double)argf);
            }
            if (t < 15) g_mu[t] = (float)((double)t * (20.0/14.0));
        }
    }

    float xi[RWARP], yi[RWARP], zi[RWARP];
    #pragma unroll
    for (int r = 0; r < RWARP; r++){
        xi[r] = Xb[(r0+r)*3+0];
        yi[r] = Xb[(r0+r)*3+1];
        zi[r] = Xb[(r0+r)*3+2];
    }

    unsigned long long h0[RWARP], h1[RWARP];
    #pragma unroll
    for (int r = 0; r < RWARP; r++){ h0[r]=0ull; h1[r]=0ull; }

    // ---- pass 1: register histogram of d^2 octave bins ----
    #pragma unroll 2
    for (int m = 0; m < NN/32; m++){
        int j = m*32 + lane;
        float xj = __ldg(&Xb[j*3+0]);
        float yj = __ldg(&Xb[j*3+1]);
        float zj = __ldg(&Xb[j*3+2]);
        #pragma unroll
        for (int r = 0; r < RWARP; r++){
            float d2 = d2_exact(xi[r],yi[r],zi[r],xj,yj,zj);
            int bin = (int)(__float_as_uint(d2) >> 23) - 126;
            bin = max(0, min(15, bin));
            unsigned long long one = 1ull << ((bin & 7) << 3);
            if (bin < 8) h0[r] += one; else h1[r] += one;
        }
    }

    // ---- per-row threshold bin via warp tree over packed counters ----
    int Tb[RWARP];
    const unsigned long long M8 = 0x00FF00FF00FF00FFull;
    #pragma unroll
    for (int r = 0; r < RWARP; r++){
        unsigned long long a0 =  h0[r]       & M8;
        unsigned long long a1 = (h0[r] >> 8) & M8;
        unsigned long long a2 =  h1[r]       & M8;
        unsigned long long a3 = (h1[r] >> 8) & M8;
        #pragma unroll
        for (int off = 16; off; off >>= 1){
            a0 += __shfl_xor_sync(0xffffffffu, a0, off);
            a1 += __shfl_xor_sync(0xffffffffu, a1, off);
            a2 += __shfl_xor_sync(0xffffffffu, a2, off);
            a3 += __shfl_xor_sync(0xffffffffu, a3, off);
        }
        int cum = 0, T = 15;
        #pragma unroll
        for (int bb = 0; bb < 16; bb++){
            unsigned long long src = (bb < 8) ? ((bb & 1) ? a1 : a0)
                                              : ((bb & 1) ? a3 : a2);
            cum += (int)((src >> (((bb >> 1) & 3) << 4)) & 0xFFFFull);
            if (cum >= KK){ T = bb; break; }
        }
        Tb[r] = T;
    }

    // ---- pass 2: compact survivors (d2bits<<32 | j) via ballot prefix ----
    int cnt[RWARP];
    #pragma unroll
    for (int r = 0; r < RWARP; r++) cnt[r] = 0;

    #pragma unroll 2
    for (int m = 0; m < NN/32; m++){
        int j = m*32 + lane;
        float xj = __ldg(&Xb[j*3+0]);
        float yj = __ldg(&Xb[j*3+1]);
        float zj = __ldg(&Xb[j*3+2]);
        #pragma unroll
        for (int r = 0; r < RWARP; r++){
            float d2 = d2_exact(xi[r],yi[r],zi[r],xj,yj,zj);
            int bin = (int)(__float_as_uint(d2) >> 23) - 126;
            bin = max(0, min(15, bin));
            bool keep = (bin <= Tb[r]);
            unsigned int mask = __ballot_sync(0xffffffffu, keep);
            if (keep){
                int pos = cnt[r] + __popc(mask & ((1u << lane) - 1u));
                if (pos < CAP3)
                    cand[w*RWARP + r][pos] =
                        ((unsigned long long)__float_as_uint(d2) << 32) | (unsigned int)j;
            }
            cnt[r] += __popc(mask);
        }
    }
    __syncwarp();

    // ---- extraction: rank-based selection on exact (D, j) keys ----
    #pragma unroll
    for (int r = 0; r < RWARP; r++){
        const int row = w*RWARP + r;
        const int c = min(cnt[r], CAP3);
        const int base = (b*NN + r0 + r)*KK;

        // convert (d2,j) -> exact key (Dbits<<32 | j), in place
        for (int idx = lane; idx < c; idx += 32){
            unsigned long long raw = cand[row][idx];
            float d2 = __uint_as_float((unsigned int)(raw >> 32));
            float D  = __fsqrt_rn(fadd_(d2, 1e-6f));
            cand[row][idx] = ((unsigned long long)__float_as_uint(D) << 32)
                           | (raw & 0xFFFFFFFFull);
        }
        __syncwarp();

        // rank = number of strictly-smaller keys (keys unique: j embedded)
        for (int idx = lane; idx < c; idx += 32){
            unsigned long long k = cand[row][idx];
            int rank = 0;
            for (int cc = 0; cc < c; cc++)
                rank += (cand[row][cc] < k) ? 1 : 0;
            if (rank < KK){
                unsigned int jj = (unsigned int)(k & 0xFFFFFFFFull);
                outD[base + rank]   = __uint_as_float((unsigned int)(k >> 32));
                outE[base + rank]   = (float)jj;
                g_eidx[base + rank] = (int)jj;
            }
        }
        __syncwarp();
    }
}

// ============================================================================
// Kernel C (merged): per-edge pos_emb (16) + gaussian smear (15) + dU (3)
// ============================================================================
#define LOG2E 1.4426950408889634f
__global__ __launch_bounds__(256) void edge_kernel(
    const float* __restrict__ X, const float* __restrict__ Dn,
    float* __restrict__ outP, float* __restrict__ outG, float* __restrict__ outO)
{
    int e = blockIdx.x*blockDim.x + threadIdx.x;
    if (e >= BB*NN*KK) return;
    int ni = e / KK;
    int i  = ni % NN;
    int b  = ni / NN;
    int j  = g_eidx[e];

    // ---- positional encodings ----
    float d = fsub_((float)j, (float)i);
    float co[8], si[8];
    #pragma unroll
    for (int m = 0; m < 8; m++){
        float ang = fmul_(d, g_freq[m]);
        sincos_red_(ang, si[m], co[m]);
    }
    float4* op = (float4*)(outP + (size_t)e*16);
    op[0] = make_float4(co[0],co[1],co[2],co[3]);
    op[1] = make_float4(co[4],co[5],co[6],co[7]);
    op[2] = make_float4(si[0],si[1],si[2],si[3]);
    op[3] = make_float4(si[4],si[5],si[6],si[7]);

    // ---- gaussian smearing ----
    float D = __ldg(&Dn[e]);
    float* og = outG + (size_t)e*15;
    #pragma unroll
    for (int m = 0; m < 15; m++){
        float tt = __fdiv_rn(fsub_(D, g_mu[m]), 1.3333333333333333f);
        og[m] = exp2f(-fmul_(tt,tt) * LOG2E);
    }

    // ---- dU ----
    const float* Xb = X + b*NN*3;
    float dx = fsub_(Xb[j*3+0], Xb[i*3+0]);
    float dy = fsub_(Xb[j*3+1], Xb[i*3+1]);
    float dz = fsub_(Xb[j*3+2], Xb[i*3+2]);
    const float* Om = g_Omat + (size_t)ni*9;
    float v0 = dot3_(Om[0],Om[1],Om[2], dx,dy,dz);
    float v1 = dot3_(Om[3],Om[4],Om[5], dx,dy,dz);
    float v2 = dot3_(Om[6],Om[7],Om[8], dx,dy,dz);
    float n = __fsqrt_rn(dot3_(v0,v1,v2,v0,v1,v2));
    n = fmaxf(n, 1e-12f);
    outO[(size_t)e*3+0] = __fdiv_rn(v0,n);
    outO[(size_t)e*3+1] = __fdiv_rn(v1,n);
    outO[(size_t)e*3+2] = __fdiv_rn(v2,n);
}

// ============================================================================
extern "C" void kernel_launch(void* const* d_in, const int* in_sizes, int n_in,
                              void* d_out, int out_size)
{
    const float* X = (const float*)d_in[0];
    float* out = (float*)d_out;

    knn_kernel<<<BB*NN/RBLK, TPB3>>>(X, out + OFF_DN, out + OFF_EI, out + OFF_AD);
    edge_kernel<<<(BB*NN*KK + 255)/256, 256>>>(X, out + OFF_DN,
                                               out + OFF_POS, out + OFF_GS, out + OFF_OF);
}